// round 6
// baseline (speedup 1.0000x reference)
#include <cuda_runtime.h>
#include <math.h>

// Problem constants
#define BB 8
#define LL 2048
#define DD 1024
#define ML (BB * LL)          // 16384 flattened rows

// ---------------- scratch (static device globals; no allocation) ----------------
__device__ float g_qp[(long)ML * DD];        // 64 MB  projected q
__device__ float g_kp[(long)ML * DD];        // 64 MB  projected k
__device__ float g_vp[(long)ML * DD];        // 64 MB  projected v
__device__ float g_att[(long)BB * LL * LL];  // 128 MB attention scores / reused for final pre-LN
__device__ float g_ao[(long)ML * DD];        // 64 MB  attention output
__device__ float g_ksum[ML];                 // key row sums (mask via ==0)
__device__ float g_qsum[ML];                 // query row sums

// ---------------- generic tiled SGEMM ----------------
// C[M,N] = alpha * A[M,K] * op(B) + bias[n] + resid[m,n]
// TRANS_B: B is [N,K] row-major (compute A*B^T). else B is [K,N] row-major.
// All of M, N multiples of 128; K multiple of 8. Batched via blockIdx.z with strides.
#define TILE 128
#define KT 8

template <bool TRANS_B>
__global__ __launch_bounds__(256, 2)
void gemm128(const float* __restrict__ A, const float* __restrict__ B,
             float* __restrict__ C,
             int M, int N, int K,
             long sA, long sB, long sC,
             float alpha,
             const float* __restrict__ bias,
             const float* __restrict__ resid, long sR)
{
    __shared__ float As[KT][TILE];
    __shared__ float Bs[KT][TILE];

    const int bz = blockIdx.z;
    A += (long)bz * sA;
    B += (long)bz * sB;
    C += (long)bz * sC;
    if (resid) resid += (long)bz * sR;

    const int tid = threadIdx.x;
    const int tx = tid & 15;         // 0..15  -> 8 cols each
    const int ty = tid >> 4;         // 0..15  -> 8 rows each
    const int rowBase = blockIdx.y * TILE;
    const int colBase = blockIdx.x * TILE;

    float acc[8][8];
#pragma unroll
    for (int i = 0; i < 8; i++)
#pragma unroll
        for (int j = 0; j < 8; j++) acc[i][j] = 0.0f;

    // A tile load mapping: 128 rows x 8 k, each thread one float4
    const int ar = tid >> 1;            // 0..127
    const int ac = (tid & 1) * 4;       // 0 or 4
    const float* Aptr = A + (long)(rowBase + ar) * K + ac;

    // B tile load mapping
    const float* Bptr;
    int bkr = 0, bnc = 0;
    if (TRANS_B) {
        Bptr = B + (long)(colBase + ar) * K + ac;    // same layout as A
    } else {
        bkr = tid >> 5;                 // k-row 0..7
        bnc = (tid & 31) * 4;           // n col
        Bptr = B + (long)bkr * N + colBase + bnc;
    }

    for (int kt = 0; kt < K; kt += KT) {
        float4 av = *(const float4*)(Aptr + kt);
        As[ac + 0][ar] = av.x;
        As[ac + 1][ar] = av.y;
        As[ac + 2][ar] = av.z;
        As[ac + 3][ar] = av.w;
        if (TRANS_B) {
            float4 bv = *(const float4*)(Bptr + kt);
            Bs[ac + 0][ar] = bv.x;
            Bs[ac + 1][ar] = bv.y;
            Bs[ac + 2][ar] = bv.z;
            Bs[ac + 3][ar] = bv.w;
        } else {
            float4 bv = *(const float4*)(Bptr + (long)kt * N);
            *(float4*)&Bs[bkr][bnc] = bv;
        }
        __syncthreads();

#pragma unroll
        for (int kk = 0; kk < KT; kk++) {
            float4 a0 = *(const float4*)&As[kk][ty * 8];
            float4 a1 = *(const float4*)&As[kk][ty * 8 + 4];
            float4 b0 = *(const float4*)&Bs[kk][tx * 8];
            float4 b1 = *(const float4*)&Bs[kk][tx * 8 + 4];
            float am[8] = {a0.x, a0.y, a0.z, a0.w, a1.x, a1.y, a1.z, a1.w};
            float bn[8] = {b0.x, b0.y, b0.z, b0.w, b1.x, b1.y, b1.z, b1.w};
#pragma unroll
            for (int i = 0; i < 8; i++)
#pragma unroll
                for (int j = 0; j < 8; j++)
                    acc[i][j] = fmaf(am[i], bn[j], acc[i][j]);
        }
        __syncthreads();
    }

    // epilogue
#pragma unroll
    for (int i = 0; i < 8; i++) {
        const long m = rowBase + ty * 8 + i;
        float out[8];
#pragma unroll
        for (int j = 0; j < 8; j++) {
            const int n = colBase + tx * 8 + j;
            float v = alpha * acc[i][j];
            if (bias) v += bias[n];
            if (resid) v += resid[m * N + n];
            out[j] = v;
        }
        float4* cp = (float4*)(C + m * N + colBase + tx * 8);
        cp[0] = make_float4(out[0], out[1], out[2], out[3]);
        cp[1] = make_float4(out[4], out[5], out[6], out[7]);
    }
}

// ---------------- block reduction helpers ----------------
__device__ __forceinline__ float block_reduce_sum(float v, float* red) {
    const int tid = threadIdx.x;
#pragma unroll
    for (int o = 16; o; o >>= 1) v += __shfl_xor_sync(0xffffffffu, v, o);
    if ((tid & 31) == 0) red[tid >> 5] = v;
    __syncthreads();
    float s = red[0];
#pragma unroll
    for (int i = 1; i < 8; i++) s += red[i];
    return s;
}

__device__ __forceinline__ float block_reduce_max(float v, float* red) {
    const int tid = threadIdx.x;
#pragma unroll
    for (int o = 16; o; o >>= 1) v = fmaxf(v, __shfl_xor_sync(0xffffffffu, v, o));
    if ((tid & 31) == 0) red[tid >> 5] = v;
    __syncthreads();
    float s = red[0];
#pragma unroll
    for (int i = 1; i < 8; i++) s = fmaxf(s, red[i]);
    return s;
}

// ---------------- row sums of raw inputs (padding masks) ----------------
__global__ void rowsum_kernel(const float* __restrict__ x, float* __restrict__ s) {
    __shared__ float red[8];
    const long r = blockIdx.x;
    const float* p = x + r * DD;
    float acc = 0.0f;
    for (int t = threadIdx.x; t < DD; t += 256) acc += p[t];
    float tot = block_reduce_sum(acc, red);
    if (threadIdx.x == 0) s[r] = tot;
}

// ---------------- masked softmax over keys (in place on g_att) ----------------
__global__ void softmax_mask_kernel(float* __restrict__ att,
                                    const float* __restrict__ ksum,
                                    const float* __restrict__ qsum) {
    __shared__ float red[8];
    const long r = blockIdx.x;          // 0..B*L-1 (query row)
    const int b = (int)(r >> 11);       // / 2048
    float* row = att + r * (long)LL;
    const float* km = ksum + (long)b * LL;
    const int tid = threadIdx.x;

    float v[8];
    float mx = -INFINITY;
#pragma unroll
    for (int t = 0; t < 8; t++) {
        const int j = tid + t * 256;
        float x = row[j];
        if (km[j] == 0.0f) x = -INFINITY;
        v[t] = x;
        mx = fmaxf(mx, x);
    }
    mx = block_reduce_max(mx, red);
    __syncthreads();

    float s = 0.0f;
#pragma unroll
    for (int t = 0; t < 8; t++) {
        float e = (v[t] == -INFINITY) ? 0.0f : __expf(v[t] - mx);
        v[t] = e;
        s += e;
    }
    s = block_reduce_sum(s, red);
    const float inv = (s > 0.0f) ? (1.0f / s) : 0.0f;
    const float zero_row = (qsum[r] == 0.0f) ? 0.0f : 1.0f;
#pragma unroll
    for (int t = 0; t < 8; t++) {
        const int j = tid + t * 256;
        row[j] = v[t] * inv * zero_row;
    }
}

// ---------------- LayerNorm (elementwise_affine=False, eps=1e-5) ----------------
__global__ void ln_kernel(const float* __restrict__ x, float* __restrict__ out) {
    __shared__ float red[8];
    const long r = blockIdx.x;
    const float* p = x + r * (long)DD;
    const int tid = threadIdx.x;
    float v[4];
#pragma unroll
    for (int t = 0; t < 4; t++) v[t] = p[tid + t * 256];

    float s = v[0] + v[1] + v[2] + v[3];
    s = block_reduce_sum(s, red);
    const float mu = s * (1.0f / DD);
    __syncthreads();

    float q = 0.0f;
#pragma unroll
    for (int t = 0; t < 4; t++) {
        const float d = v[t] - mu;
        q += d * d;
    }
    q = block_reduce_sum(q, red);
    const float rstd = rsqrtf(q * (1.0f / DD) + 1e-5f);

    float* o = out + r * (long)DD;
#pragma unroll
    for (int t = 0; t < 4; t++) o[tid + t * 256] = (v[t] - mu) * rstd;
}

// ---------------- launch ----------------
extern "C" void kernel_launch(void* const* d_in, const int* in_sizes, int n_in,
                              void* d_out, int out_size) {
    const float* q  = (const float*)d_in[0];
    const float* k  = (const float*)d_in[1];
    const float* v  = (const float*)d_in[2];
    const float* Wq = (const float*)d_in[3];
    const float* bq = (const float*)d_in[4];
    const float* Wk = (const float*)d_in[5];
    const float* bk = (const float*)d_in[6];
    const float* Wv = (const float*)d_in[7];
    const float* bv = (const float*)d_in[8];
    const float* Wo = (const float*)d_in[9];
    const float* bo = (const float*)d_in[10];
    float* out = (float*)d_out;

    float *qp, *kp, *vp, *att, *ao, *ksum, *qsum;
    cudaGetSymbolAddress((void**)&qp,   g_qp);
    cudaGetSymbolAddress((void**)&kp,   g_kp);
    cudaGetSymbolAddress((void**)&vp,   g_vp);
    cudaGetSymbolAddress((void**)&att,  g_att);
    cudaGetSymbolAddress((void**)&ao,   g_ao);
    cudaGetSymbolAddress((void**)&ksum, g_ksum);
    cudaGetSymbolAddress((void**)&qsum, g_qsum);

    const long pStride = (long)LL * DD;   // per-batch stride of projected tensors
    const long aStride = (long)LL * LL;   // per-batch stride of attention matrix

    // 1) padding masks from raw q, k
    rowsum_kernel<<<ML, 256>>>(k, ksum);
    rowsum_kernel<<<ML, 256>>>(q, qsum);

    // 2) input projections: X @ W^T + b   (M=16384, N=K=1024)
    {
        dim3 grid(DD / TILE, ML / TILE, 1), blk(256);
        gemm128<true><<<grid, blk>>>(q, Wq, qp, ML, DD, DD, 0, 0, 0, 1.0f, bq, nullptr, 0);
        gemm128<true><<<grid, blk>>>(k, Wk, kp, ML, DD, DD, 0, 0, 0, 1.0f, bk, nullptr, 0);
        gemm128<true><<<grid, blk>>>(v, Wv, vp, ML, DD, DD, 0, 0, 0, 1.0f, bv, nullptr, 0);
    }

    // 3) scores: S = (qp @ kp^T) * D^-0.5, batched over B
    {
        dim3 grid(LL / TILE, LL / TILE, BB), blk(256);
        gemm128<true><<<grid, blk>>>(qp, kp, att, LL, LL, DD,
                                     pStride, pStride, aStride,
                                     0.03125f /* 1/sqrt(1024) */, nullptr, nullptr, 0);
    }

    // 4) masked softmax (in place)
    softmax_mask_kernel<<<ML, 256>>>(att, ksum, qsum);

    // 5) O = att @ vp  (NN, batched)
    {
        dim3 grid(DD / TILE, LL / TILE, BB), blk(256);
        gemm128<false><<<grid, blk>>>(att, vp, ao, LL, DD, LL,
                                      aStride, pStride, pStride,
                                      1.0f, nullptr, nullptr, 0);
    }

    // 6) output projection + residual (qp): reuse g_att as pre-LN buffer
    {
        dim3 grid(DD / TILE, ML / TILE, 1), blk(256);
        gemm128<true><<<grid, blk>>>(ao, Wo, att, ML, DD, DD, 0, 0, 0,
                                     1.0f, bo, qp, 0);
    }

    // 7) LayerNorm -> output
    ln_kernel<<<ML, 256>>>(att, out);
}

// round 7
// speedup vs baseline: 2.0144x; 2.0144x over previous
#include <cuda_runtime.h>
#include <cuda_bf16.h>
#include <math.h>
#include <stdint.h>

// Problem constants
#define BB 8
#define LL 2048
#define DD 1024
#define ML (BB * LL)          // 16384 flattened rows

// ---------------- scratch (static device globals; no allocation) ----------------
__device__ float g_qp[(long)ML * DD];        // 64 MB  projected q
__device__ float g_kp[(long)ML * DD];        // 64 MB  projected k
__device__ float g_vp[(long)ML * DD];        // 64 MB  projected v
__device__ float g_vpT[(long)ML * DD];       // 64 MB  vp transposed per batch [D][L]
__device__ float g_att[(long)BB * LL * LL];  // 128 MB attention scores / reused pre-LN
__device__ float g_ao[(long)ML * DD];        // 64 MB  attention output
__device__ float g_ksum[ML];                 // key row sums (mask via ==0)
__device__ float g_qsum[ML];                 // query row sums

// ---------------- bf16x2-split tensor-core GEMM ----------------
// C[M,N] = alpha * A[M,K] * B^T + bias[n] + resid[m,n]
// A row-major [M][K], B row-major [N][K] (i.e., TN GEMM). Batched via blockIdx.z.
// fp32 inputs converted on the fly to (hi, lo) bf16; products hh + hl + lh give
// ~fp32 accuracy with tensor-core throughput.
#define BM 128
#define BN 128
#define BK 32
#define SROW 48                 // padded smem row stride (bf16 elems): 96B, 16B-aligned rows
#define SMEM_BYTES (4 * 128 * SROW * 2)

__device__ __forceinline__ void ldsm4(uint32_t* r, uint32_t addr) {
    asm volatile("ldmatrix.sync.aligned.m8n8.x4.shared.b16 {%0,%1,%2,%3}, [%4];"
                 : "=r"(r[0]), "=r"(r[1]), "=r"(r[2]), "=r"(r[3]) : "r"(addr));
}

__device__ __forceinline__ void mma16816(float* c, const uint32_t* a, uint32_t b0, uint32_t b1) {
    asm volatile("mma.sync.aligned.m16n8k16.row.col.f32.bf16.bf16.f32 "
                 "{%0,%1,%2,%3}, {%4,%5,%6,%7}, {%8,%9}, {%0,%1,%2,%3};"
                 : "+f"(c[0]), "+f"(c[1]), "+f"(c[2]), "+f"(c[3])
                 : "r"(a[0]), "r"(a[1]), "r"(a[2]), "r"(a[3]), "r"(b0), "r"(b1));
}

__device__ __forceinline__ void cvt_store(__nv_bfloat16* H, __nv_bfloat16* L,
                                          int idx, float4 v) {
    __nv_bfloat16 h0 = __float2bfloat16(v.x);
    __nv_bfloat16 h1 = __float2bfloat16(v.y);
    __nv_bfloat16 h2 = __float2bfloat16(v.z);
    __nv_bfloat16 h3 = __float2bfloat16(v.w);
    __nv_bfloat16 l0 = __float2bfloat16(v.x - __bfloat162float(h0));
    __nv_bfloat16 l1 = __float2bfloat16(v.y - __bfloat162float(h1));
    __nv_bfloat16 l2 = __float2bfloat16(v.z - __bfloat162float(h2));
    __nv_bfloat16 l3 = __float2bfloat16(v.w - __bfloat162float(h3));
    union U { __nv_bfloat16 b[4]; uint2 u; };
    U hu, lu;
    hu.b[0] = h0; hu.b[1] = h1; hu.b[2] = h2; hu.b[3] = h3;
    lu.b[0] = l0; lu.b[1] = l1; lu.b[2] = l2; lu.b[3] = l3;
    *(uint2*)(H + idx) = hu.u;
    *(uint2*)(L + idx) = lu.u;
}

__global__ __launch_bounds__(256)
void bgemm_tn(const float* __restrict__ A, const float* __restrict__ B,
              float* __restrict__ C,
              int M, int N, int K,
              long sA, long sB, long sC,
              float alpha,
              const float* __restrict__ bias,
              const float* __restrict__ resid, long sR)
{
    extern __shared__ __align__(16) char smem_raw[];
    __nv_bfloat16* Ah = (__nv_bfloat16*)smem_raw;
    __nv_bfloat16* Al = Ah + 128 * SROW;
    __nv_bfloat16* Bh = Al + 128 * SROW;
    __nv_bfloat16* Bl = Bh + 128 * SROW;

    const int bz = blockIdx.z;
    A += (long)bz * sA;
    B += (long)bz * sB;
    C += (long)bz * sC;
    if (resid) resid += (long)bz * sR;

    const int tid  = threadIdx.x;
    const int lane = tid & 31;
    const int warp = tid >> 5;
    const int warpM = warp & 1;    // 2 along M  (64 rows each)
    const int warpN = warp >> 1;   // 4 along N  (32 cols each)
    const int rowBase = blockIdx.y * BM;
    const int colBase = blockIdx.x * BN;

    // global load mapping: each thread loads 16 consecutive K-elems of one row
    const int lr = tid >> 1;              // 0..127
    const int lc = (tid & 1) * 16;        // 0 or 16
    const float* Ap = A + (long)(rowBase + lr) * K + lc;
    const float* Bp = B + (long)(colBase + lr) * K + lc;

    float acc[4][4][4];
#pragma unroll
    for (int i = 0; i < 4; i++)
#pragma unroll
        for (int j = 0; j < 4; j++)
#pragma unroll
            for (int t = 0; t < 4; t++) acc[i][j][t] = 0.0f;

    float4 pa[4], pb[4];
#pragma unroll
    for (int i = 0; i < 4; i++) {
        pa[i] = *(const float4*)(Ap + 4 * i);
        pb[i] = *(const float4*)(Bp + 4 * i);
    }

    uint32_t sAh = (uint32_t)__cvta_generic_to_shared(Ah);
    uint32_t sAl = (uint32_t)__cvta_generic_to_shared(Al);
    uint32_t sBh = (uint32_t)__cvta_generic_to_shared(Bh);
    uint32_t sBl = (uint32_t)__cvta_generic_to_shared(Bl);

    for (int kt = 0; kt < K; kt += BK) {
        // stage current prefetched tile into smem (fp32 -> bf16 hi/lo)
#pragma unroll
        for (int i = 0; i < 4; i++) {
            cvt_store(Ah, Al, lr * SROW + lc + 4 * i, pa[i]);
            cvt_store(Bh, Bl, lr * SROW + lc + 4 * i, pb[i]);
        }
        __syncthreads();

        // prefetch next tile
        if (kt + BK < K) {
#pragma unroll
            for (int i = 0; i < 4; i++) {
                pa[i] = *(const float4*)(Ap + kt + BK + 4 * i);
                pb[i] = *(const float4*)(Bp + kt + BK + 4 * i);
            }
        }

        // MMA over the two k16 steps of this K-tile
#pragma unroll
        for (int ks = 0; ks < 2; ks++) {
            const int kb = ks * 16;
            // ldmatrix lane addressing: row = base + (lane & 15), col = kb + 8*(lane>>4)
            const int rsel = (lane & 15);
            const int csel = kb + 8 * (lane >> 4);

            uint32_t ah[4][4], al[4][4];
#pragma unroll
            for (int mf = 0; mf < 4; mf++) {
                const int ar = warpM * 64 + mf * 16 + rsel;
                const uint32_t off = (uint32_t)(ar * SROW + csel) * 2;
                ldsm4(ah[mf], sAh + off);
                ldsm4(al[mf], sAl + off);
            }
            uint32_t bh[2][4], bl[2][4];
#pragma unroll
            for (int g = 0; g < 2; g++) {
                const int br = warpN * 32 + g * 16 + rsel;
                const uint32_t off = (uint32_t)(br * SROW + csel) * 2;
                ldsm4(bh[g], sBh + off);
                ldsm4(bl[g], sBl + off);
            }
#pragma unroll
            for (int mf = 0; mf < 4; mf++) {
#pragma unroll
                for (int nf = 0; nf < 4; nf++) {
                    const int g = nf >> 1, o = nf & 1;
                    // hi*hi
                    mma16816(acc[mf][nf], ah[mf], bh[g][o], bh[g][o + 2]);
                    // hi*lo
                    mma16816(acc[mf][nf], ah[mf], bl[g][o], bl[g][o + 2]);
                    // lo*hi
                    mma16816(acc[mf][nf], al[mf], bh[g][o], bh[g][o + 2]);
                }
            }
        }
        __syncthreads();
    }

    // epilogue: C frag layout: c0,c1 at (r, c),(r, c+1); c2,c3 at (r+8, c),(r+8, c+1)
#pragma unroll
    for (int mf = 0; mf < 4; mf++) {
#pragma unroll
        for (int nf = 0; nf < 4; nf++) {
            const long r0 = rowBase + warpM * 64 + mf * 16 + (lane >> 2);
            const int  c0 = colBase + warpN * 32 + nf * 8 + (lane & 3) * 2;
            float v0 = alpha * acc[mf][nf][0];
            float v1 = alpha * acc[mf][nf][1];
            float v2 = alpha * acc[mf][nf][2];
            float v3 = alpha * acc[mf][nf][3];
            if (bias) {
                v0 += bias[c0]; v1 += bias[c0 + 1];
                v2 += bias[c0]; v3 += bias[c0 + 1];
            }
            if (resid) {
                v0 += resid[r0 * N + c0];       v1 += resid[r0 * N + c0 + 1];
                v2 += resid[(r0 + 8) * N + c0]; v3 += resid[(r0 + 8) * N + c0 + 1];
            }
            *(float2*)(C + r0 * N + c0)       = make_float2(v0, v1);
            *(float2*)(C + (r0 + 8) * N + c0) = make_float2(v2, v3);
        }
    }
}

// ---------------- transpose vp -> vpT (per batch [L][D] -> [D][L]) ----------------
__global__ void transpose_kernel(const float* __restrict__ in, float* __restrict__ out) {
    __shared__ float t[32][33];
    const int b = blockIdx.z;
    const float* ip = in + (long)b * LL * DD;
    float* op = out + (long)b * LL * DD;
    const int dx = blockIdx.x * 32;   // D base
    const int ly = blockIdx.y * 32;   // L base
    const int tx = threadIdx.x, ty = threadIdx.y;  // 32 x 8
#pragma unroll
    for (int i = 0; i < 4; i++)
        t[ty + i * 8][tx] = ip[(long)(ly + ty + i * 8) * DD + dx + tx];
    __syncthreads();
#pragma unroll
    for (int i = 0; i < 4; i++)
        op[(long)(dx + ty + i * 8) * LL + ly + tx] = t[tx][ty + i * 8];
}

// ---------------- block reduction helpers ----------------
__device__ __forceinline__ float block_reduce_sum(float v, float* red) {
    const int tid = threadIdx.x;
#pragma unroll
    for (int o = 16; o; o >>= 1) v += __shfl_xor_sync(0xffffffffu, v, o);
    if ((tid & 31) == 0) red[tid >> 5] = v;
    __syncthreads();
    float s = red[0];
#pragma unroll
    for (int i = 1; i < 8; i++) s += red[i];
    return s;
}

__device__ __forceinline__ float block_reduce_max(float v, float* red) {
    const int tid = threadIdx.x;
#pragma unroll
    for (int o = 16; o; o >>= 1) v = fmaxf(v, __shfl_xor_sync(0xffffffffu, v, o));
    if ((tid & 31) == 0) red[tid >> 5] = v;
    __syncthreads();
    float s = red[0];
#pragma unroll
    for (int i = 1; i < 8; i++) s = fmaxf(s, red[i]);
    return s;
}

// ---------------- row sums of raw inputs (padding masks) ----------------
__global__ void rowsum_kernel(const float* __restrict__ x, float* __restrict__ s) {
    __shared__ float red[8];
    const long r = blockIdx.x;
    const float* p = x + r * DD;
    float acc = 0.0f;
    for (int t = threadIdx.x; t < DD; t += 256) acc += p[t];
    float tot = block_reduce_sum(acc, red);
    if (threadIdx.x == 0) s[r] = tot;
}

// ---------------- masked softmax over keys (in place on g_att) ----------------
__global__ void softmax_mask_kernel(float* __restrict__ att,
                                    const float* __restrict__ ksum,
                                    const float* __restrict__ qsum) {
    __shared__ float red[8];
    const long r = blockIdx.x;          // 0..B*L-1 (query row)
    const int b = (int)(r >> 11);       // / 2048
    float* row = att + r * (long)LL;
    const float* km = ksum + (long)b * LL;
    const int tid = threadIdx.x;

    float v[8];
    float mx = -INFINITY;
#pragma unroll
    for (int t = 0; t < 8; t++) {
        const int j = tid + t * 256;
        float x = row[j];
        if (km[j] == 0.0f) x = -INFINITY;
        v[t] = x;
        mx = fmaxf(mx, x);
    }
    mx = block_reduce_max(mx, red);
    __syncthreads();

    float s = 0.0f;
#pragma unroll
    for (int t = 0; t < 8; t++) {
        float e = (v[t] == -INFINITY) ? 0.0f : __expf(v[t] - mx);
        v[t] = e;
        s += e;
    }
    s = block_reduce_sum(s, red);
    const float inv = (s > 0.0f) ? (1.0f / s) : 0.0f;
    const float zero_row = (qsum[r] == 0.0f) ? 0.0f : 1.0f;
#pragma unroll
    for (int t = 0; t < 8; t++) {
        const int j = tid + t * 256;
        row[j] = v[t] * inv * zero_row;
    }
}

// ---------------- LayerNorm (elementwise_affine=False, eps=1e-5) ----------------
__global__ void ln_kernel(const float* __restrict__ x, float* __restrict__ out) {
    __shared__ float red[8];
    const long r = blockIdx.x;
    const float* p = x + r * (long)DD;
    const int tid = threadIdx.x;
    float v[4];
#pragma unroll
    for (int t = 0; t < 4; t++) v[t] = p[tid + t * 256];

    float s = v[0] + v[1] + v[2] + v[3];
    s = block_reduce_sum(s, red);
    const float mu = s * (1.0f / DD);
    __syncthreads();

    float q = 0.0f;
#pragma unroll
    for (int t = 0; t < 4; t++) {
        const float d = v[t] - mu;
        q += d * d;
    }
    q = block_reduce_sum(q, red);
    const float rstd = rsqrtf(q * (1.0f / DD) + 1e-5f);

    float* o = out + r * (long)DD;
#pragma unroll
    for (int t = 0; t < 4; t++) o[tid + t * 256] = (v[t] - mu) * rstd;
}

// ---------------- launch ----------------
extern "C" void kernel_launch(void* const* d_in, const int* in_sizes, int n_in,
                              void* d_out, int out_size) {
    const float* q  = (const float*)d_in[0];
    const float* k  = (const float*)d_in[1];
    const float* v  = (const float*)d_in[2];
    const float* Wq = (const float*)d_in[3];
    const float* bq = (const float*)d_in[4];
    const float* Wk = (const float*)d_in[5];
    const float* bk = (const float*)d_in[6];
    const float* Wv = (const float*)d_in[7];
    const float* bv = (const float*)d_in[8];
    const float* Wo = (const float*)d_in[9];
    const float* bo = (const float*)d_in[10];
    float* out = (float*)d_out;

    float *qp, *kp, *vp, *vpT, *att, *ao, *ksum, *qsum;
    cudaGetSymbolAddress((void**)&qp,   g_qp);
    cudaGetSymbolAddress((void**)&kp,   g_kp);
    cudaGetSymbolAddress((void**)&vp,   g_vp);
    cudaGetSymbolAddress((void**)&vpT,  g_vpT);
    cudaGetSymbolAddress((void**)&att,  g_att);
    cudaGetSymbolAddress((void**)&ao,   g_ao);
    cudaGetSymbolAddress((void**)&ksum, g_ksum);
    cudaGetSymbolAddress((void**)&qsum, g_qsum);

    const long pStride = (long)LL * DD;   // per-batch stride of projected tensors
    const long aStride = (long)LL * LL;   // per-batch stride of attention matrix

    // 1) padding masks from raw q, k
    rowsum_kernel<<<ML, 256>>>(k, ksum);
    rowsum_kernel<<<ML, 256>>>(q, qsum);

    // 2) input projections: X @ W^T + b   (M=16384, N=K=1024)
    {
        dim3 grid(DD / BN, ML / BM, 1), blk(256);
        bgemm_tn<<<grid, blk, SMEM_BYTES>>>(q, Wq, qp, ML, DD, DD, 0, 0, 0, 1.0f, bq, nullptr, 0);
        bgemm_tn<<<grid, blk, SMEM_BYTES>>>(k, Wk, kp, ML, DD, DD, 0, 0, 0, 1.0f, bk, nullptr, 0);
        bgemm_tn<<<grid, blk, SMEM_BYTES>>>(v, Wv, vp, ML, DD, DD, 0, 0, 0, 1.0f, bv, nullptr, 0);
    }

    // 3) transpose vp -> vpT per batch
    {
        dim3 grid(DD / 32, LL / 32, BB), blk(32, 8);
        transpose_kernel<<<grid, blk>>>(vp, vpT);
    }

    // 4) scores: S = (qp @ kp^T) * D^-0.5, batched over B
    {
        dim3 grid(LL / BN, LL / BM, BB), blk(256);
        bgemm_tn<<<grid, blk, SMEM_BYTES>>>(qp, kp, att, LL, LL, DD,
                                            pStride, pStride, aStride,
                                            0.03125f /* 1/sqrt(1024) */, nullptr, nullptr, 0);
    }

    // 5) masked softmax (in place)
    softmax_mask_kernel<<<ML, 256>>>(att, ksum, qsum);

    // 6) O = att @ vpT^T  (TN form: B = vpT [D][L]), batched
    {
        dim3 grid(DD / BN, LL / BM, BB), blk(256);
        bgemm_tn<<<grid, blk, SMEM_BYTES>>>(att, vpT, ao, LL, DD, LL,
                                            aStride, pStride, pStride,
                                            1.0f, nullptr, nullptr, 0);
    }

    // 7) output projection + residual (qp): reuse g_att as pre-LN buffer
    {
        dim3 grid(DD / BN, ML / BM, 1), blk(256);
        bgemm_tn<<<grid, blk, SMEM_BYTES>>>(ao, Wo, att, ML, DD, DD, 0, 0, 0,
                                            1.0f, bo, qp, 0);
    }

    // 8) LayerNorm -> output
    ln_kernel<<<ML, 256>>>(att, out);
}

// round 10
// speedup vs baseline: 2.0744x; 1.0298x over previous
#include <cuda_runtime.h>
#include <cuda_bf16.h>
#include <math.h>
#include <stdint.h>

// Problem constants
#define BB 8
#define LL 2048
#define DD 1024
#define ML (BB * LL)          // 16384 flattened rows

// ---------------- scratch (static device globals; no allocation) ----------------
__device__ float g_qp[(long)ML * DD];        // projected q
__device__ float g_kp[(long)ML * DD];        // projected k
__device__ float g_vp[(long)ML * DD];        // projected v
__device__ float g_vpT[(long)ML * DD];       // vp transposed per batch [D][L]
__device__ float g_att[(long)BB * LL * LL];  // attention scores / reused pre-LN
__device__ float g_ao[(long)ML * DD];        // attention output
__device__ float g_ksum[ML];
__device__ float g_qsum[ML];

// ================= bf16-split tensor-core GEMM (mma.sync path) =================
// C[M,N] = alpha * A * B^T + bias[n] + resid[m,n]
// A row-major [M][K] fp32, B row-major [N][K] fp32 (TN). Batched via blockIdx.z.
// fp32 -> (hi,lo) bf16 split; acc += Ah*Bh + Ah*Bl + Al*Bh (fp32 accum on tensor pipe).
//
// Block tile 128(M) x 256(N) x 16(K). 8 warps = 2(M) x 4(N), warp tile 64x64.
// smem rows: 16 bf16 padded to 24 (48B stride; 48=16*3 coprime with 8 -> conflict-free
// ldmatrix and clean 16B alignment). Double-buffered.

#define SROW 24                        // smem row stride in bf16 elems (48 B)
#define ROWS_BUF 768                   // Ah(128)+Al(128)+Bh(256)+Bl(256)
#define BUF_BYTES (ROWS_BUF * SROW * 2)        // 36864
#define SMEM_BYTES (2 * BUF_BYTES)             // 73728
#define OFF_AL (128 * SROW)            // element offsets of sections
#define OFF_BH (256 * SROW)
#define OFF_BL (512 * SROW)

__device__ __forceinline__ void ldsm4(uint32_t* r, uint32_t addr) {
    asm volatile("ldmatrix.sync.aligned.m8n8.x4.shared.b16 {%0,%1,%2,%3}, [%4];"
                 : "=r"(r[0]), "=r"(r[1]), "=r"(r[2]), "=r"(r[3]) : "r"(addr));
}
__device__ __forceinline__ void mma16816(float* c, const uint32_t* a, uint32_t b0, uint32_t b1) {
    asm volatile("mma.sync.aligned.m16n8k16.row.col.f32.bf16.bf16.f32 "
                 "{%0,%1,%2,%3}, {%4,%5,%6,%7}, {%8,%9}, {%0,%1,%2,%3};"
                 : "+f"(c[0]), "+f"(c[1]), "+f"(c[2]), "+f"(c[3])
                 : "r"(a[0]), "r"(a[1]), "r"(a[2]), "r"(a[3]), "r"(b0), "r"(b1));
}

__device__ __forceinline__ void cvt4(float4 v, uint2& hi, uint2& lo) {
    union { __nv_bfloat16 b[4]; uint2 u; } H, L;
    H.b[0] = __float2bfloat16(v.x); L.b[0] = __float2bfloat16(v.x - __bfloat162float(H.b[0]));
    H.b[1] = __float2bfloat16(v.y); L.b[1] = __float2bfloat16(v.y - __bfloat162float(H.b[1]));
    H.b[2] = __float2bfloat16(v.z); L.b[2] = __float2bfloat16(v.z - __bfloat162float(H.b[2]));
    H.b[3] = __float2bfloat16(v.w); L.b[3] = __float2bfloat16(v.w - __bfloat162float(H.b[3]));
    hi = H.u; lo = L.u;
}

// load one 16-wide K-slab: A 128 rows, B 256 rows. 1536 float4 / 256 thr = 6 each.
// i=0,1 -> A rows; i=2..5 -> B rows (uniform branch per i).
__device__ __forceinline__ void stage_load(float4* p, const float* At, const float* Bt,
                                           int K, int kt, int tid) {
#pragma unroll
    for (int i = 0; i < 6; i++) {
        const int f = tid + i * 256;
        if (f < 512) {
            const int row = f >> 2, c4 = f & 3;
            p[i] = *(const float4*)(At + (long)row * K + kt + c4 * 4);
        } else {
            const int fb = f - 512;
            const int row = fb >> 2, c4 = fb & 3;
            p[i] = *(const float4*)(Bt + (long)row * K + kt + c4 * 4);
        }
    }
}

__device__ __forceinline__ void stage_store(__nv_bfloat16* buf, const float4* p, int tid) {
#pragma unroll
    for (int i = 0; i < 6; i++) {
        const int f = tid + i * 256;
        uint2 hi, lo;
        cvt4(p[i], hi, lo);
        if (f < 512) {
            const int row = f >> 2, c4 = f & 3;
            *(uint2*)(buf + row * SROW + c4 * 4)          = hi;
            *(uint2*)(buf + OFF_AL + row * SROW + c4 * 4) = lo;
        } else {
            const int fb = f - 512;
            const int row = fb >> 2, c4 = fb & 3;
            *(uint2*)(buf + OFF_BH + row * SROW + c4 * 4) = hi;
            *(uint2*)(buf + OFF_BL + row * SROW + c4 * 4) = lo;
        }
    }
}

__global__ __launch_bounds__(256, 1)
void bgemm_tn(const float* __restrict__ A, const float* __restrict__ B,
              float* __restrict__ C, int K, int Nld,
              long sA, long sB, long sC, float alpha,
              const float* __restrict__ bias,
              const float* __restrict__ resid, long sR)
{
    extern __shared__ __align__(16) char smem_raw[];
    __nv_bfloat16* sm0 = (__nv_bfloat16*)smem_raw;

    const int bz = blockIdx.z;
    A += (long)bz * sA;
    B += (long)bz * sB;
    C += (long)bz * sC;
    if (resid) resid += (long)bz * sR;

    const int tid  = threadIdx.x;
    const int lane = tid & 31;
    const int warp = tid >> 5;
    const int warpM = warp & 1;     // 2 along M (64 rows)
    const int warpN = warp >> 1;    // 4 along N (64 cols)
    const int rowBase = blockIdx.y * 128;
    const int colBase = blockIdx.x * 256;

    const float* At = A + (long)rowBase * K;
    const float* Bt = B + (long)colBase * K;

    float acc[4][8][4];
#pragma unroll
    for (int i = 0; i < 4; i++)
#pragma unroll
        for (int j = 0; j < 8; j++)
#pragma unroll
            for (int t = 0; t < 4; t++) acc[i][j][t] = 0.0f;

    // ldmatrix lane addressing
    const int rsel = lane & 15;
    const int csel = 8 * (lane >> 4);                 // 0 or 8 elems
    const uint32_t smbase = (uint32_t)__cvta_generic_to_shared(sm0);
    // per-warp base byte offsets (row part added per fragment)
    const uint32_t aOff = (uint32_t)(((warpM * 64 + rsel) * SROW + csel) * 2);
    const uint32_t bOff = (uint32_t)(((OFF_BH) + (warpN * 64 + rsel) * SROW + csel) * 2);

    const int T = K / 16;
    float4 p[6];
    stage_load(p, At, Bt, K, 0, tid);
    stage_store(sm0, p, tid);
    __syncthreads();

    for (int t = 0; t < T; t++) {
        if (t + 1 < T) stage_load(p, At, Bt, K, (t + 1) * 16, tid);

        const uint32_t bufB = smbase + (uint32_t)((t & 1) * BUF_BYTES);

        uint32_t ah[4][4], al[4][4];
#pragma unroll
        for (int mf = 0; mf < 4; mf++) {
            const uint32_t ra = bufB + aOff + (uint32_t)(mf * 16 * SROW * 2);
            ldsm4(ah[mf], ra);
            ldsm4(al[mf], ra + (uint32_t)(OFF_AL * 2));
        }
#pragma unroll
        for (int g = 0; g < 4; g++) {
            uint32_t bh[4], bl[4];
            const uint32_t rb = bufB + bOff + (uint32_t)(g * 16 * SROW * 2);
            ldsm4(bh, rb);
            ldsm4(bl, rb + (uint32_t)(256 * SROW * 2));
#pragma unroll
            for (int mf = 0; mf < 4; mf++) {
#pragma unroll
                for (int o = 0; o < 2; o++) {
                    float* c = acc[mf][g * 2 + o];
                    mma16816(c, ah[mf], bh[o], bh[o + 2]);
                    mma16816(c, ah[mf], bl[o], bl[o + 2]);
                    mma16816(c, al[mf], bh[o], bh[o + 2]);
                }
            }
        }

        if (t + 1 < T) stage_store(sm0 + ((t + 1) & 1) * (BUF_BYTES / 2), p, tid);
        __syncthreads();
    }

    // epilogue
#pragma unroll
    for (int mf = 0; mf < 4; mf++) {
#pragma unroll
        for (int nf = 0; nf < 8; nf++) {
            const long r0 = rowBase + warpM * 64 + mf * 16 + (lane >> 2);
            const int  c0 = colBase + warpN * 64 + nf * 8 + (lane & 3) * 2;
            float v0 = alpha * acc[mf][nf][0];
            float v1 = alpha * acc[mf][nf][1];
            float v2 = alpha * acc[mf][nf][2];
            float v3 = alpha * acc[mf][nf][3];
            if (bias) {
                v0 += bias[c0]; v1 += bias[c0 + 1];
                v2 += bias[c0]; v3 += bias[c0 + 1];
            }
            if (resid) {
                v0 += resid[r0 * Nld + c0];       v1 += resid[r0 * Nld + c0 + 1];
                v2 += resid[(r0 + 8) * Nld + c0]; v3 += resid[(r0 + 8) * Nld + c0 + 1];
            }
            *(float2*)(C + r0 * Nld + c0)       = make_float2(v0, v1);
            *(float2*)(C + (r0 + 8) * Nld + c0) = make_float2(v2, v3);
        }
    }
}

// ---------------- transpose vp -> vpT (per batch [L][D] -> [D][L]) ----------------
__global__ void transpose_kernel(const float* __restrict__ in, float* __restrict__ out) {
    __shared__ float t[32][33];
    const int b = blockIdx.z;
    const float* ip = in + (long)b * LL * DD;
    float* op = out + (long)b * LL * DD;
    const int dx = blockIdx.x * 32;
    const int ly = blockIdx.y * 32;
    const int tx = threadIdx.x, ty = threadIdx.y;  // 32 x 8
#pragma unroll
    for (int i = 0; i < 4; i++)
        t[ty + i * 8][tx] = ip[(long)(ly + ty + i * 8) * DD + dx + tx];
    __syncthreads();
#pragma unroll
    for (int i = 0; i < 4; i++)
        op[(long)(dx + ty + i * 8) * LL + ly + tx] = t[tx][ty + i * 8];
}

// ---------------- block reduction helpers ----------------
__device__ __forceinline__ float block_reduce_sum(float v, float* red) {
    const int tid = threadIdx.x;
#pragma unroll
    for (int o = 16; o; o >>= 1) v += __shfl_xor_sync(0xffffffffu, v, o);
    if ((tid & 31) == 0) red[tid >> 5] = v;
    __syncthreads();
    float s = red[0];
#pragma unroll
    for (int i = 1; i < 8; i++) s += red[i];
    return s;
}
__device__ __forceinline__ float block_reduce_max(float v, float* red) {
    const int tid = threadIdx.x;
#pragma unroll
    for (int o = 16; o; o >>= 1) v = fmaxf(v, __shfl_xor_sync(0xffffffffu, v, o));
    if ((tid & 31) == 0) red[tid >> 5] = v;
    __syncthreads();
    float s = red[0];
#pragma unroll
    for (int i = 1; i < 8; i++) s = fmaxf(s, red[i]);
    return s;
}

// ---------------- row sums of raw inputs (padding masks) ----------------
__global__ void rowsum_kernel(const float* __restrict__ x, float* __restrict__ s) {
    __shared__ float red[8];
    const long r = blockIdx.x;
    const float* p = x + r * DD;
    float acc = 0.0f;
    for (int t = threadIdx.x; t < DD; t += 256) acc += p[t];
    float tot = block_reduce_sum(acc, red);
    if (threadIdx.x == 0) s[r] = tot;
}

// ---------------- masked softmax over keys (in place on g_att) ----------------
__global__ void softmax_mask_kernel(float* __restrict__ att,
                                    const float* __restrict__ ksum,
                                    const float* __restrict__ qsum) {
    __shared__ float red[8];
    const long r = blockIdx.x;
    const int b = (int)(r >> 11);
    float* row = att + r * (long)LL;
    const float* km = ksum + (long)b * LL;
    const int tid = threadIdx.x;

    float v[8];
    float mx = -INFINITY;
#pragma unroll
    for (int t = 0; t < 8; t++) {
        const int j = tid + t * 256;
        float x = row[j];
        if (km[j] == 0.0f) x = -INFINITY;
        v[t] = x;
        mx = fmaxf(mx, x);
    }
    mx = block_reduce_max(mx, red);
    __syncthreads();

    float s = 0.0f;
#pragma unroll
    for (int t = 0; t < 8; t++) {
        float e = (v[t] == -INFINITY) ? 0.0f : __expf(v[t] - mx);
        v[t] = e;
        s += e;
    }
    s = block_reduce_sum(s, red);
    const float inv = (s > 0.0f) ? (1.0f / s) : 0.0f;
    const float zero_row = (qsum[r] == 0.0f) ? 0.0f : 1.0f;
#pragma unroll
    for (int t = 0; t < 8; t++) {
        const int j = tid + t * 256;
        row[j] = v[t] * inv * zero_row;
    }
}

// ---------------- LayerNorm ----------------
__global__ void ln_kernel(const float* __restrict__ x, float* __restrict__ out) {
    __shared__ float red[8];
    const long r = blockIdx.x;
    const float* p = x + r * (long)DD;
    const int tid = threadIdx.x;
    float v[4];
#pragma unroll
    for (int t = 0; t < 4; t++) v[t] = p[tid + t * 256];

    float s = v[0] + v[1] + v[2] + v[3];
    s = block_reduce_sum(s, red);
    const float mu = s * (1.0f / DD);
    __syncthreads();

    float q = 0.0f;
#pragma unroll
    for (int t = 0; t < 4; t++) {
        const float d = v[t] - mu;
        q += d * d;
    }
    q = block_reduce_sum(q, red);
    const float rstd = rsqrtf(q * (1.0f / DD) + 1e-5f);

    float* o = out + r * (long)DD;
#pragma unroll
    for (int t = 0; t < 4; t++) o[tid + t * 256] = (v[t] - mu) * rstd;
}

// ---------------- launch ----------------
extern "C" void kernel_launch(void* const* d_in, const int* in_sizes, int n_in,
                              void* d_out, int out_size) {
    const float* q  = (const float*)d_in[0];
    const float* k  = (const float*)d_in[1];
    const float* v  = (const float*)d_in[2];
    const float* Wq = (const float*)d_in[3];
    const float* bq = (const float*)d_in[4];
    const float* Wk = (const float*)d_in[5];
    const float* bk = (const float*)d_in[6];
    const float* Wv = (const float*)d_in[7];
    const float* bv = (const float*)d_in[8];
    const float* Wo = (const float*)d_in[9];
    const float* bo = (const float*)d_in[10];
    float* out = (float*)d_out;

    float *qp, *kp, *vp, *vpT, *att, *ao, *ksum, *qsum;
    cudaGetSymbolAddress((void**)&qp,   g_qp);
    cudaGetSymbolAddress((void**)&kp,   g_kp);
    cudaGetSymbolAddress((void**)&vp,   g_vp);
    cudaGetSymbolAddress((void**)&vpT,  g_vpT);
    cudaGetSymbolAddress((void**)&att,  g_att);
    cudaGetSymbolAddress((void**)&ao,   g_ao);
    cudaGetSymbolAddress((void**)&ksum, g_ksum);
    cudaGetSymbolAddress((void**)&qsum, g_qsum);

    cudaFuncSetAttribute(bgemm_tn, cudaFuncAttributeMaxDynamicSharedMemorySize, SMEM_BYTES);

    const long pStride = (long)LL * DD;
    const long aStride = (long)LL * LL;

    // 1) padding masks from raw q, k
    rowsum_kernel<<<ML, 256>>>(k, ksum);
    rowsum_kernel<<<ML, 256>>>(q, qsum);

    // 2) input projections: X @ W^T + b   (M=16384, N=K=1024)
    {
        dim3 g(DD / 256, ML / 128, 1);
        bgemm_tn<<<g, 256, SMEM_BYTES>>>(q, Wq, qp, DD, DD, 0, 0, 0, 1.0f, bq, nullptr, 0);
        bgemm_tn<<<g, 256, SMEM_BYTES>>>(k, Wk, kp, DD, DD, 0, 0, 0, 1.0f, bk, nullptr, 0);
        bgemm_tn<<<g, 256, SMEM_BYTES>>>(v, Wv, vp, DD, DD, 0, 0, 0, 1.0f, bv, nullptr, 0);
    }

    // 3) transpose vp -> vpT per batch
    {
        dim3 g(DD / 32, LL / 32, BB), blk(32, 8);
        transpose_kernel<<<g, blk>>>(vp, vpT);
    }

    // 4) scores: S = (qp @ kp^T) * D^-0.5, batched
    {
        dim3 g(LL / 256, LL / 128, BB);
        bgemm_tn<<<g, 256, SMEM_BYTES>>>(qp, kp, att, DD, LL,
                                         pStride, pStride, aStride,
                                         0.03125f, nullptr, nullptr, 0);
    }

    // 5) masked softmax (in place)
    softmax_mask_kernel<<<ML, 256>>>(att, ksum, qsum);

    // 6) O = att @ vpT^T  (TN: B = vpT [D][L]), batched, K = L
    {
        dim3 g(DD / 256, LL / 128, BB);
        bgemm_tn<<<g, 256, SMEM_BYTES>>>(att, vpT, ao, LL, DD,
                                         aStride, pStride, pStride,
                                         1.0f, nullptr, nullptr, 0);
    }

    // 7) output projection + residual (qp): reuse g_att as pre-LN buffer
    {
        dim3 g(DD / 256, ML / 128, 1);
        bgemm_tn<<<g, 256, SMEM_BYTES>>>(ao, Wo, att, DD, DD, 0, 0, 0,
                                         1.0f, bo, qp, 0);
    }

    // 8) LayerNorm -> output
    ln_kernel<<<ML, 256>>>(att, out);
}

// round 11
// speedup vs baseline: 2.4602x; 1.1860x over previous
#include <cuda_runtime.h>
#include <cuda_bf16.h>
#include <math.h>
#include <stdint.h>

// Problem constants
#define BB 8
#define LL 2048
#define DD 1024
#define ML (BB * LL)          // 16384 flattened rows

typedef __nv_bfloat16 bf16;

// ---------------- scratch (static device globals; no allocation) ----------------
__device__ float g_qp[(long)ML * DD];          // projected q fp32 (residual)
__device__ float g_vp[(long)ML * DD];          // projected v fp32; reused as pre-LN buffer
__device__ float g_att[(long)BB * LL * LL];    // fp32 attention scores
__device__ bf16 g_qh[(long)ML * DD],  g_ql[(long)ML * DD];     // raw q hi/lo
__device__ bf16 g_kh[(long)ML * DD],  g_kl[(long)ML * DD];     // raw k hi/lo
__device__ bf16 g_vh[(long)ML * DD],  g_vl[(long)ML * DD];     // raw v hi/lo
__device__ bf16 g_Wh[4][(long)DD * DD], g_Wl[4][(long)DD * DD];
__device__ bf16 g_qph[(long)ML * DD], g_qpl[(long)ML * DD];
__device__ bf16 g_kph[(long)ML * DD], g_kpl[(long)ML * DD];
__device__ bf16 g_vpTh[(long)ML * DD], g_vpTl[(long)ML * DD];  // vp^T per batch [D][L]
__device__ bf16 g_atth[(long)BB * LL * LL], g_attl[(long)BB * LL * LL];
__device__ bf16 g_aoh[(long)ML * DD], g_aol[(long)ML * DD];
__device__ float g_ksum[ML], g_qsum[ML];

// ================= bf16-split tensor-core GEMM, cp.async pipeline =================
// C = alpha * A * B^T (+bias[n]) (+resid[m,n]); A=[M][K], B=[N][K] given as bf16 hi/lo.
// acc += Ah*Bh + Ah*Bl + Al*Bh (fp32 accum). Block 128(M)x256(N)x32(K), 8 warps 2x4,
// warp tile 64x64. 3-stage cp.async pipeline. Smem row = 32 bf16 data, 80B stride
// (5x16B, coprime with 8 -> conflict-free ldmatrix).

#define SROWB 80
#define ST_AL (128 * SROWB)        // 10240
#define ST_BH (256 * SROWB)        // 20480
#define ST_BL (512 * SROWB)        // 40960
#define STAGE_BYTES (768 * SROWB)  // 61440
#define NSTAGE 3
#define SMEM_BYTES (NSTAGE * STAGE_BYTES)   // 184320

__device__ __forceinline__ void ldsm4(uint32_t* r, uint32_t addr) {
    asm volatile("ldmatrix.sync.aligned.m8n8.x4.shared.b16 {%0,%1,%2,%3}, [%4];"
                 : "=r"(r[0]), "=r"(r[1]), "=r"(r[2]), "=r"(r[3]) : "r"(addr));
}
__device__ __forceinline__ void mma16816(float* c, const uint32_t* a, uint32_t b0, uint32_t b1) {
    asm volatile("mma.sync.aligned.m16n8k16.row.col.f32.bf16.bf16.f32 "
                 "{%0,%1,%2,%3}, {%4,%5,%6,%7}, {%8,%9}, {%0,%1,%2,%3};"
                 : "+f"(c[0]), "+f"(c[1]), "+f"(c[2]), "+f"(c[3])
                 : "r"(a[0]), "r"(a[1]), "r"(a[2]), "r"(a[3]), "r"(b0), "r"(b1));
}
__device__ __forceinline__ void cpa16(uint32_t dst, const void* src) {
    asm volatile("cp.async.cg.shared.global [%0], [%1], 16;" :: "r"(dst), "l"(src));
}
__device__ __forceinline__ uint32_t pack2(float a, float b) {
    union { bf16 h[2]; uint32_t u; } t;
    t.h[0] = __float2bfloat16(a);
    t.h[1] = __float2bfloat16(b);
    return t.u;
}
__device__ __forceinline__ uint32_t pack2lo(float a, float b) {
    bf16 ha = __float2bfloat16(a), hb = __float2bfloat16(b);
    union { bf16 h[2]; uint32_t u; } t;
    t.h[0] = __float2bfloat16(a - __bfloat162float(ha));
    t.h[1] = __float2bfloat16(b - __bfloat162float(hb));
    return t.u;
}

// issue one 32-wide K-slab (A 128 rows hi+lo, B 256 rows hi+lo) via cp.async
__device__ __forceinline__ void issue_stage(uint32_t sdst,
        const bf16* Ath, const bf16* Atl, const bf16* Bth, const bf16* Btl,
        int K, int kt, int tid)
{
#pragma unroll
    for (int i = 0; i < 12; i++) {
        const int cid = tid + i * 256;        // 0..3071
        const int row = cid >> 2;             // 0..767
        const int ch  = cid & 3;              // 16B chunk within 64B row
        const uint32_t dst = sdst + (uint32_t)(row * SROWB + ch * 16);
        const bf16* src;
        if (i < 2)       src = Ath + (long)row * K + kt + ch * 8;
        else if (i < 4)  src = Atl + (long)(row - 128) * K + kt + ch * 8;
        else if (i < 8)  src = Bth + (long)(row - 256) * K + kt + ch * 8;
        else             src = Btl + (long)(row - 512) * K + kt + ch * 8;
        cpa16(dst, src);
    }
    asm volatile("cp.async.commit_group;");
}

__global__ __launch_bounds__(256, 1)
void bgemm_async(const bf16* __restrict__ Ah_, const bf16* __restrict__ Al_,
                 const bf16* __restrict__ Bh_, const bf16* __restrict__ Bl_,
                 float* __restrict__ Cf, bf16* __restrict__ Ch, bf16* __restrict__ Cl,
                 int K, int Nld,
                 long sA, long sB, long sC, float alpha,
                 const float* __restrict__ bias,
                 const float* __restrict__ resid)
{
    extern __shared__ __align__(16) char smem[];
    const int tid  = threadIdx.x;
    const int lane = tid & 31;
    const int warp = tid >> 5;
    const int warpM = warp & 1;
    const int warpN = warp >> 1;
    const int bz = blockIdx.z;
    const int rowBase = blockIdx.y * 128;
    const int colBase = blockIdx.x * 256;

    const bf16* Ath = Ah_ + (long)bz * sA + (long)rowBase * K;
    const bf16* Atl = Al_ + (long)bz * sA + (long)rowBase * K;
    const bf16* Bth = Bh_ + (long)bz * sB + (long)colBase * K;
    const bf16* Btl = Bl_ + (long)bz * sB + (long)colBase * K;

    float acc[4][8][4];
#pragma unroll
    for (int i = 0; i < 4; i++)
#pragma unroll
        for (int j = 0; j < 8; j++)
#pragma unroll
            for (int t = 0; t < 4; t++) acc[i][j][t] = 0.0f;

    const uint32_t smb = (uint32_t)__cvta_generic_to_shared(smem);
    const int rsel = lane & 15;
    const int hsel = (lane >> 4) * 16;      // 0 / 16 bytes
    const uint32_t aOff = (uint32_t)((warpM * 64 + rsel) * SROWB + hsel);
    const uint32_t bOff = (uint32_t)(ST_BH + (warpN * 64 + rsel) * SROWB + hsel);

    const int T = K / 32;
    issue_stage(smb,               Ath, Atl, Bth, Btl, K, 0,  tid);
    issue_stage(smb + STAGE_BYTES, Ath, Atl, Bth, Btl, K, 32, tid);

    for (int t = 0; t < T; t++) {
        if (t + 2 < T) { asm volatile("cp.async.wait_group 1;"); }
        else           { asm volatile("cp.async.wait_group 0;"); }
        __syncthreads();

        const uint32_t sb = smb + (uint32_t)((t % NSTAGE) * STAGE_BYTES);
#pragma unroll
        for (int ks = 0; ks < 2; ks++) {
            const uint32_t kb = ks * 32;   // byte offset of k16 step within 64B row
            uint32_t ah[4][4], al[4][4];
#pragma unroll
            for (int mf = 0; mf < 4; mf++) {
                const uint32_t ra = sb + aOff + (uint32_t)(mf * 16 * SROWB) + kb;
                ldsm4(ah[mf], ra);
                ldsm4(al[mf], ra + ST_AL);
            }
#pragma unroll
            for (int g = 0; g < 4; g++) {
                uint32_t bh[4], bl[4];
                const uint32_t rb = sb + bOff + (uint32_t)(g * 16 * SROWB) + kb;
                ldsm4(bh, rb);
                ldsm4(bl, rb + (uint32_t)(ST_BL - ST_BH));
#pragma unroll
                for (int mf = 0; mf < 4; mf++) {
#pragma unroll
                    for (int o = 0; o < 2; o++) {
                        float* c = acc[mf][g * 2 + o];
                        mma16816(c, ah[mf], bh[o], bh[o + 2]);
                        mma16816(c, ah[mf], bl[o], bl[o + 2]);
                        mma16816(c, al[mf], bh[o], bh[o + 2]);
                    }
                }
            }
        }

        if (t + 2 < T)
            issue_stage(smb + (uint32_t)(((t + 2) % NSTAGE) * STAGE_BYTES),
                        Ath, Atl, Bth, Btl, K, (t + 2) * 32, tid);
    }

    // ---------------- epilogue ----------------
    float* Cfp = Cf ? Cf + (long)bz * sC : nullptr;
    bf16*  Chp = Ch ? Ch + (long)bz * sC : nullptr;
    bf16*  Clp = Cl ? Cl + (long)bz * sC : nullptr;

#pragma unroll
    for (int mf = 0; mf < 4; mf++) {
#pragma unroll
        for (int nf = 0; nf < 8; nf++) {
            const long r0 = rowBase + warpM * 64 + mf * 16 + (lane >> 2);
            const int  c0 = colBase + warpN * 64 + nf * 8 + (lane & 3) * 2;
            float v0 = alpha * acc[mf][nf][0];
            float v1 = alpha * acc[mf][nf][1];
            float v2 = alpha * acc[mf][nf][2];
            float v3 = alpha * acc[mf][nf][3];
            if (bias) {
                v0 += bias[c0]; v1 += bias[c0 + 1];
                v2 += bias[c0]; v3 += bias[c0 + 1];
            }
            if (resid) {
                v0 += resid[r0 * Nld + c0];       v1 += resid[r0 * Nld + c0 + 1];
                v2 += resid[(r0 + 8) * Nld + c0]; v3 += resid[(r0 + 8) * Nld + c0 + 1];
            }
            if (Cfp) {
                *(float2*)(Cfp + r0 * Nld + c0)       = make_float2(v0, v1);
                *(float2*)(Cfp + (r0 + 8) * Nld + c0) = make_float2(v2, v3);
            }
            if (Chp) {
                *(uint32_t*)(Chp + r0 * Nld + c0)       = pack2(v0, v1);
                *(uint32_t*)(Chp + (r0 + 8) * Nld + c0) = pack2(v2, v3);
                *(uint32_t*)(Clp + r0 * Nld + c0)       = pack2lo(v0, v1);
                *(uint32_t*)(Clp + (r0 + 8) * Nld + c0) = pack2lo(v2, v3);
            }
        }
    }
}

// ---------------- block reduction helper ----------------
__device__ __forceinline__ float block_reduce_sum(float v, float* red) {
    const int tid = threadIdx.x;
#pragma unroll
    for (int o = 16; o; o >>= 1) v += __shfl_xor_sync(0xffffffffu, v, o);
    if ((tid & 31) == 0) red[tid >> 5] = v;
    __syncthreads();
    float s = red[0];
#pragma unroll
    for (int i = 1; i < 8; i++) s += red[i];
    return s;
}
__device__ __forceinline__ float block_reduce_max(float v, float* red) {
    const int tid = threadIdx.x;
#pragma unroll
    for (int o = 16; o; o >>= 1) v = fmaxf(v, __shfl_xor_sync(0xffffffffu, v, o));
    if ((tid & 31) == 0) red[tid >> 5] = v;
    __syncthreads();
    float s = red[0];
#pragma unroll
    for (int i = 1; i < 8; i++) s = fmaxf(s, red[i]);
    return s;
}

// ---------------- convert fp32 row -> bf16 hi/lo (+ optional row sum) ----------------
__global__ void conv_rowsum(const float* __restrict__ x, bf16* __restrict__ xh,
                            bf16* __restrict__ xl, float* __restrict__ sum) {
    __shared__ float red[8];
    const long r = blockIdx.x;
    const int tid = threadIdx.x;
    const float4 v = ((const float4*)(x + r * DD))[tid];
    union { bf16 h[4]; uint2 u; } H, L;
    H.h[0] = __float2bfloat16(v.x); L.h[0] = __float2bfloat16(v.x - __bfloat162float(H.h[0]));
    H.h[1] = __float2bfloat16(v.y); L.h[1] = __float2bfloat16(v.y - __bfloat162float(H.h[1]));
    H.h[2] = __float2bfloat16(v.z); L.h[2] = __float2bfloat16(v.z - __bfloat162float(H.h[2]));
    H.h[3] = __float2bfloat16(v.w); L.h[3] = __float2bfloat16(v.w - __bfloat162float(H.h[3]));
    ((uint2*)(xh + r * DD))[tid] = H.u;
    ((uint2*)(xl + r * DD))[tid] = L.u;
    const float s = block_reduce_sum(v.x + v.y + v.z + v.w, red);
    if (sum && tid == 0) sum[r] = s;
}

// ---------------- elementwise fp32 -> bf16 hi/lo (weights) ----------------
__global__ void conv_elem(const float* __restrict__ x, bf16* __restrict__ xh,
                          bf16* __restrict__ xl, long n4) {
    const long i = (long)blockIdx.x * 256 + threadIdx.x;
    if (i >= n4) return;
    const float4 v = ((const float4*)x)[i];
    union { bf16 h[4]; uint2 u; } H, L;
    H.h[0] = __float2bfloat16(v.x); L.h[0] = __float2bfloat16(v.x - __bfloat162float(H.h[0]));
    H.h[1] = __float2bfloat16(v.y); L.h[1] = __float2bfloat16(v.y - __bfloat162float(H.h[1]));
    H.h[2] = __float2bfloat16(v.z); L.h[2] = __float2bfloat16(v.z - __bfloat162float(H.h[2]));
    H.h[3] = __float2bfloat16(v.w); L.h[3] = __float2bfloat16(v.w - __bfloat162float(H.h[3]));
    ((uint2*)xh)[i] = H.u;
    ((uint2*)xl)[i] = L.u;
}

// ---------------- transpose vp -> vpT hi/lo (per batch [L][D] -> [D][L]) ----------------
__global__ void transpose_kernel(const float* __restrict__ in,
                                 bf16* __restrict__ oh, bf16* __restrict__ ol) {
    __shared__ float t[32][33];
    const int b = blockIdx.z;
    const float* ip = in + (long)b * LL * DD;
    const long ob = (long)b * LL * DD;
    const int dx = blockIdx.x * 32;
    const int ly = blockIdx.y * 32;
    const int tx = threadIdx.x, ty = threadIdx.y;  // 32 x 8
#pragma unroll
    for (int i = 0; i < 4; i++)
        t[ty + i * 8][tx] = ip[(long)(ly + ty + i * 8) * DD + dx + tx];
    __syncthreads();
#pragma unroll
    for (int i = 0; i < 4; i++) {
        const float v = t[tx][ty + i * 8];
        const bf16 h = __float2bfloat16(v);
        const long idx = ob + (long)(dx + ty + i * 8) * LL + ly + tx;
        oh[idx] = h;
        ol[idx] = __float2bfloat16(v - __bfloat162float(h));
    }
}

// ---------------- masked softmax: fp32 scores -> bf16 hi/lo probabilities ----------------
__global__ void softmax_mask_kernel(const float* __restrict__ att,
                                    bf16* __restrict__ ph, bf16* __restrict__ pl,
                                    const float* __restrict__ ksum,
                                    const float* __restrict__ qsum) {
    __shared__ float red[8];
    const long r = blockIdx.x;
    const int b = (int)(r >> 11);
    const float* row = att + r * (long)LL;
    const float* km = ksum + (long)b * LL;
    const int tid = threadIdx.x;

    float v[8];
    float mx = -INFINITY;
#pragma unroll
    for (int t = 0; t < 8; t++) {
        const int j = tid + t * 256;
        float x = row[j];
        if (km[j] == 0.0f) x = -INFINITY;
        v[t] = x;
        mx = fmaxf(mx, x);
    }
    mx = block_reduce_max(mx, red);
    __syncthreads();

    float s = 0.0f;
#pragma unroll
    for (int t = 0; t < 8; t++) {
        float e = (v[t] == -INFINITY) ? 0.0f : __expf(v[t] - mx);
        v[t] = e;
        s += e;
    }
    s = block_reduce_sum(s, red);
    const float inv = (s > 0.0f) ? (1.0f / s) : 0.0f;
    const float zr = (qsum[r] == 0.0f) ? 0.0f : 1.0f;
#pragma unroll
    for (int t = 0; t < 8; t++) {
        const long j = r * (long)LL + tid + t * 256;
        const float p = v[t] * inv * zr;
        const bf16 h = __float2bfloat16(p);
        ph[j] = h;
        pl[j] = __float2bfloat16(p - __bfloat162float(h));
    }
}

// ---------------- LayerNorm ----------------
__global__ void ln_kernel(const float* __restrict__ x, float* __restrict__ out) {
    __shared__ float red[8];
    const long r = blockIdx.x;
    const float* p = x + r * (long)DD;
    const int tid = threadIdx.x;
    float v[4];
#pragma unroll
    for (int t = 0; t < 4; t++) v[t] = p[tid + t * 256];

    float s = v[0] + v[1] + v[2] + v[3];
    s = block_reduce_sum(s, red);
    const float mu = s * (1.0f / DD);
    __syncthreads();

    float q = 0.0f;
#pragma unroll
    for (int t = 0; t < 4; t++) {
        const float d = v[t] - mu;
        q += d * d;
    }
    q = block_reduce_sum(q, red);
    const float rstd = rsqrtf(q * (1.0f / DD) + 1e-5f);

    float* o = out + r * (long)DD;
#pragma unroll
    for (int t = 0; t < 4; t++) o[tid + t * 256] = (v[t] - mu) * rstd;
}

// ---------------- launch ----------------
extern "C" void kernel_launch(void* const* d_in, const int* in_sizes, int n_in,
                              void* d_out, int out_size) {
    const float* q  = (const float*)d_in[0];
    const float* k  = (const float*)d_in[1];
    const float* v  = (const float*)d_in[2];
    const float* Wq = (const float*)d_in[3];
    const float* bq = (const float*)d_in[4];
    const float* Wk = (const float*)d_in[5];
    const float* bk = (const float*)d_in[6];
    const float* Wv = (const float*)d_in[7];
    const float* bv = (const float*)d_in[8];
    const float* Wo = (const float*)d_in[9];
    const float* bo = (const float*)d_in[10];
    float* out = (float*)d_out;

    float *qp, *vp, *att, *ksum, *qsum;
    bf16 *qh, *ql, *kh, *kl, *vh, *vl, *Wh, *Wl;
    bf16 *qph, *qpl, *kph, *kpl, *vpTh, *vpTl, *atth, *attl, *aoh, *aol;
    cudaGetSymbolAddress((void**)&qp,   g_qp);
    cudaGetSymbolAddress((void**)&vp,   g_vp);
    cudaGetSymbolAddress((void**)&att,  g_att);
    cudaGetSymbolAddress((void**)&ksum, g_ksum);
    cudaGetSymbolAddress((void**)&qsum, g_qsum);
    cudaGetSymbolAddress((void**)&qh,   g_qh);
    cudaGetSymbolAddress((void**)&ql,   g_ql);
    cudaGetSymbolAddress((void**)&kh,   g_kh);
    cudaGetSymbolAddress((void**)&kl,   g_kl);
    cudaGetSymbolAddress((void**)&vh,   g_vh);
    cudaGetSymbolAddress((void**)&vl,   g_vl);
    cudaGetSymbolAddress((void**)&Wh,   g_Wh);
    cudaGetSymbolAddress((void**)&Wl,   g_Wl);
    cudaGetSymbolAddress((void**)&qph,  g_qph);
    cudaGetSymbolAddress((void**)&qpl,  g_qpl);
    cudaGetSymbolAddress((void**)&kph,  g_kph);
    cudaGetSymbolAddress((void**)&kpl,  g_kpl);
    cudaGetSymbolAddress((void**)&vpTh, g_vpTh);
    cudaGetSymbolAddress((void**)&vpTl, g_vpTl);
    cudaGetSymbolAddress((void**)&atth, g_atth);
    cudaGetSymbolAddress((void**)&attl, g_attl);
    cudaGetSymbolAddress((void**)&aoh,  g_aoh);
    cudaGetSymbolAddress((void**)&aol,  g_aol);

    cudaFuncSetAttribute(bgemm_async, cudaFuncAttributeMaxDynamicSharedMemorySize, SMEM_BYTES);

    const long WSZ = (long)DD * DD;
    const long pStride = (long)LL * DD;
    const long aStride = (long)LL * LL;

    // 1) convert raw inputs to bf16 hi/lo + padding-mask row sums
    conv_rowsum<<<ML, 256>>>(k, kh, kl, ksum);
    conv_rowsum<<<ML, 256>>>(q, qh, ql, qsum);
    conv_rowsum<<<ML, 256>>>(v, vh, vl, nullptr);

    // 2) convert weights
    {
        const long n4 = WSZ / 4;
        const int g = (int)((n4 + 255) / 256);
        conv_elem<<<g, 256>>>(Wq, Wh + 0 * WSZ, Wl + 0 * WSZ, n4);
        conv_elem<<<g, 256>>>(Wk, Wh + 1 * WSZ, Wl + 1 * WSZ, n4);
        conv_elem<<<g, 256>>>(Wv, Wh + 2 * WSZ, Wl + 2 * WSZ, n4);
        conv_elem<<<g, 256>>>(Wo, Wh + 3 * WSZ, Wl + 3 * WSZ, n4);
    }

    // 3) input projections (M=16384, N=K=1024)
    {
        dim3 g(DD / 256, ML / 128, 1);
        bgemm_async<<<g, 256, SMEM_BYTES>>>(qh, ql, Wh + 0 * WSZ, Wl + 0 * WSZ,
                                            qp, qph, qpl, DD, DD, 0, 0, 0, 1.0f, bq, nullptr);
        bgemm_async<<<g, 256, SMEM_BYTES>>>(kh, kl, Wh + 1 * WSZ, Wl + 1 * WSZ,
                                            nullptr, kph, kpl, DD, DD, 0, 0, 0, 1.0f, bk, nullptr);
        bgemm_async<<<g, 256, SMEM_BYTES>>>(vh, vl, Wh + 2 * WSZ, Wl + 2 * WSZ,
                                            vp, nullptr, nullptr, DD, DD, 0, 0, 0, 1.0f, bv, nullptr);
    }

    // 4) transpose vp -> vpT hi/lo per batch
    {
        dim3 g(DD / 32, LL / 32, BB), blk(32, 8);
        transpose_kernel<<<g, blk>>>(vp, vpTh, vpTl);
    }

    // 5) scores: S = (qp @ kp^T) * D^-0.5, batched
    {
        dim3 g(LL / 256, LL / 128, BB);
        bgemm_async<<<g, 256, SMEM_BYTES>>>(qph, qpl, kph, kpl,
                                            att, nullptr, nullptr, DD, LL,
                                            pStride, pStride, aStride,
                                            0.03125f, nullptr, nullptr);
    }

    // 6) masked softmax -> bf16 hi/lo probabilities
    softmax_mask_kernel<<<ML, 256>>>(att, atth, attl, ksum, qsum);

    // 7) O = P @ vpT^T  (TN: B = vpT [D][L]), batched, K = L
    {
        dim3 g(DD / 256, LL / 128, BB);
        bgemm_async<<<g, 256, SMEM_BYTES>>>(atth, attl, vpTh, vpTl,
                                            nullptr, aoh, aol, LL, DD,
                                            aStride, pStride, pStride,
                                            1.0f, nullptr, nullptr);
    }

    // 8) output projection + bias + residual(qp fp32) -> pre-LN (reuse g_vp)
    {
        dim3 g(DD / 256, ML / 128, 1);
        bgemm_async<<<g, 256, SMEM_BYTES>>>(aoh, aol, Wh + 3 * WSZ, Wl + 3 * WSZ,
                                            vp, nullptr, nullptr, DD, DD, 0, 0, 0,
                                            1.0f, bo, qp);
    }

    // 9) LayerNorm -> output
    ln_kernel<<<ML, 256>>>(vp, out);
}